// round 15
// baseline (speedup 1.0000x reference)
#include <cuda_runtime.h>
#include <math.h>
#include <stdint.h>

// ---------------- problem constants ----------------
#define BATCH   128
#define IN_DIM  128
#define HID     512
#define STK     64
#define GD      2048            // 4*HID gate rows
#define KIN     (IN_DIM + STK)  // 192
#define KTOT    (KIN + HID)     // 704 combined K
#define MAXT    259
#define NSTEPS  259
#define PH1_LAST 128            // t<=128 uses x[t]; t>=129 x==0
#define OUT_T0  129
#define RDIM    194             // STK + IN_DIM + 2

#define NKSTEP  88              // 704/8 global k-steps
#define N8TOT   256             // 2048/8 n8 tiles

// ---------------- persistent device state ----------------
// B weights in interleaved mma fragment layout: [n8][ks][lane*4 + {bh0,bh1,bl0,bl1}]
__device__ __align__(16) float  g_Bf[N8TOT * NKSTEP * 128];
__device__ __align__(16) float  g_bias[GD];            // gate-interleaved (n = 4*j+gate)
__device__ __align__(16) float  g_WrT[HID * RDIM];     // Wr transposed: [k][r]
__device__ __align__(16) float  g_h[2][BATCH * HID];   // plain h (read by K2 phase)
__device__ __align__(16) float2 g_hHL[2][BATCH * HID]; // (hi,lo), k-permuted in 8-groups
__device__ __align__(16) float2 g_rtHL[BATCH * STK];   // k-permuted
__device__ __align__(16) float2 g_xHL[(PH1_LAST + 1) * BATCH * IN_DIM];  // k-permuted
__device__ float  g_c[BATCH * HID];
__device__ float  g_s[BATCH * MAXT];
__device__ float  g_V[BATCH * MAXT * STK];
__device__ int    g_cnt[NSTEPS * 4];                   // per-(t, bm-group) completion

// k-permutation within 8-groups: puts a thread's two k-halves adjacent (LDS.128)
__device__ __host__ __forceinline__ int permk(int k) {
    return (k & ~7) | ((k & 3) << 1) | ((k >> 2) & 1);
}

__device__ __forceinline__ uint32_t f2tf(float v) {
    uint32_t r;
    asm("cvt.rna.tf32.f32 %0, %1;" : "=r"(r) : "f"(v));
    return r;
}

__device__ __forceinline__ float2 splitHL(float v) {
    uint32_t hi = f2tf(v);
    return make_float2(__uint_as_float(hi), v - __uint_as_float(hi));
}

__device__ __forceinline__ void mma_tf32(float* c, const uint32_t* a, const uint32_t* b) {
    asm volatile(
        "mma.sync.aligned.m16n8k8.row.col.f32.tf32.tf32.f32 "
        "{%0,%1,%2,%3}, {%4,%5,%6,%7}, {%8,%9}, {%0,%1,%2,%3};\n"
        : "+f"(c[0]), "+f"(c[1]), "+f"(c[2]), "+f"(c[3])
        : "r"(a[0]), "r"(a[1]), "r"(a[2]), "r"(a[3]),
          "r"(b[0]), "r"(b[1]));
}

__device__ __forceinline__ void cp16(void* smem_dst, const void* gmem_src) {
    unsigned d = (unsigned)__cvta_generic_to_shared(smem_dst);
    asm volatile("cp.async.cg.shared.global [%0], [%1], 16;" :: "r"(d), "l"(gmem_src));
}

// ---------------- shared-memory layouts ----------------
struct GS {                       // gates phase (3-stage pipeline)
    float2 sA[3][32 * 34];        // [row][ks*8 + kcol*2 + half], stride 34 f2
    float  sB[3][2048];           // 4 tiles x 512 floats per stage
};                                // 26112 + 24576 = 50688 B
struct K2S {                      // readout/stack phase (overlays GS)
    float hsh[2][HID];
    float osh[2][RDIM];
    float s_ut[2], s_dt[2];
    float ssuf[272], sorig[272], aA[272];
    float ctot[16];
    float part[4][STK];
    float redm[8], redv[2], redl[2];
};

// ---------------- prep: format weights, pre-split inputs, zero state --------
__global__ void k_prep(const float* __restrict__ x,
                       const float* __restrict__ Wih, const float* __restrict__ bih,
                       const float* __restrict__ Whh, const float* __restrict__ bhh,
                       const float* __restrict__ Wr)
{
    int idx = blockIdx.x * blockDim.x + threadIdx.x;
    int nthreads = gridDim.x * blockDim.x;

    // gates weights -> gate-interleaved -> interleaved tf32 hi/lo fragments
    for (int i = idx; i < GD * KTOT; i += nthreads) {
        int n = i / KTOT, k = i - n * KTOT;
        int j = n >> 2, gate = n & 3;
        int src = gate * HID + j;
        float v = (k < KIN) ? Wih[src * KIN + k] : Whh[src * HID + (k - KIN)];
        uint32_t hi = f2tf(v);
        float lo = v - __uint_as_float(hi);
        int n8 = n >> 3, g = n & 7;
        int ks = k >> 3, kk = k & 7, tig = kk & 3, kh = kk >> 2;
        int lane = g * 4 + tig;
        int base = (n8 * NKSTEP + ks) * 128 + lane * 4 + kh;
        g_Bf[base]     = __uint_as_float(hi);
        g_Bf[base + 2] = lo;
    }
    for (int n = idx; n < GD; n += nthreads) {
        int j = n >> 2, gate = n & 3;
        g_bias[n] = bih[gate * HID + j] + bhh[gate * HID + j];
    }
    for (int i = idx; i < HID * RDIM; i += nthreads) {
        int k = i / RDIM, r = i - k * RDIM;
        g_WrT[i] = Wr[r * HID + k];
    }
    // pre-split + permute x (phase-1 steps only)
    const int XN = (PH1_LAST + 1) * BATCH * IN_DIM;
    for (int i = idx; i < XN; i += nthreads) {
        int k = i % IN_DIM;
        g_xHL[i - k + permk(k)] = splitHL(x[i]);
    }
    // zero recurrent state + counters
    for (int i = idx; i < BATCH * HID; i += nthreads) {
        g_hHL[0][i] = make_float2(0.f, 0.f);
        g_h[0][i] = 0.f;
        g_c[i] = 0.f;
    }
    for (int i = idx; i < BATCH * STK; i += nthreads) g_rtHL[i] = make_float2(0.f, 0.f);
    for (int i = idx; i < BATCH * MAXT; i += nthreads) g_s[i] = 0.f;
    for (int i = idx; i < NSTEPS * 4; i += nthreads) g_cnt[i] = 0;
}

// ---------------- fused per-step kernel: gates GEMM+cell, then readout ------
// 256 blocks x 256 thr. Gates: block = (bn = bx&63 -> 32 gate cols, bm = bx>>6
// -> 32 batches). 8 warps (2M x 4N), warp m16n8, 3xTF32, 3-stage cp.async,
// one barrier/iter. Blocks 0..63 then run the readout/stack phase for 2
// batches each after spinning on the h-completion counter of their bm-group.
__global__ void __launch_bounds__(256, 2)
k_step(int t, const float* __restrict__ br, float* __restrict__ out)
{
    extern __shared__ __align__(16) char dynbuf[];
    GS* gs = reinterpret_cast<GS*>(dynbuf);

    const int tid  = threadIdx.x;
    const int lane = tid & 31;
    const int warp = tid >> 5;
    const int bx = blockIdx.x;
    const int bn = bx & 63;
    const int bm = bx >> 6;
    const int bm0 = bm * 32;
    const int bn0 = bn * 32;
    const int n8base = bn * 4;

    const int cur = t & 1;
    const float2* __restrict__ hHL = g_hHL[cur];
    float*  __restrict__ hnew   = g_h[cur ^ 1];
    float2* __restrict__ hnewHL = g_hHL[cur ^ 1];

    const int cBeg = (t <= PH1_LAST) ? 0 : 4;   // phase 2: x chunks are zero
    const int nC = 22 - cBeg;

    const int mw  = warp >> 2;   // 0..1 m16 row
    const int nwl = warp & 3;    // 0..3 n8 tile

    // staging geometry
    const int aRow0 = tid >> 4;          // 0..15
    const int aSeg  = (tid & 15) * 2;    // float2 offset (16B granule)
    const int bTile0 = tid >> 7;         // 0..1
    const int bSeg   = tid & 127;        // float4 index in tile-chunk

    auto stage = [&](int s, int c) {
        const int k0 = c * 32;
#pragma unroll
        for (int e = 0; e < 2; e++) {
            int row = aRow0 + e * 16;
            int b = bm0 + row;
            const float2* src;
            if (k0 < IN_DIM)   src = g_xHL + ((size_t)t * BATCH + b) * IN_DIM + k0;
            else if (k0 < KIN) src = g_rtHL + b * STK + (k0 - IN_DIM);
            else               src = hHL + b * HID + (k0 - KIN);
            cp16(&gs->sA[s][row * 34 + aSeg], src + aSeg);
        }
#pragma unroll
        for (int e = 0; e < 2; e++) {
            int tile = bTile0 + e * 2;
            const float4* src = reinterpret_cast<const float4*>(g_Bf)
                + ((size_t)(n8base + tile) * NKSTEP + c * 4) * 32 + bSeg;
            cp16(&gs->sB[s][tile * 512 + bSeg * 4], src);
        }
        asm volatile("cp.async.commit_group;");
    };

    float acc[4] = {0.f, 0.f, 0.f, 0.f};
    const int aIdx0 = (mw * 16 + (lane >> 2)) * 17 + (lane & 3);  // float4 units

    stage(0, cBeg);
    stage(1, cBeg + 1);

    for (int it = 0; it < nC; ++it) {
        const int s = it % 3;
        if (it + 1 < nC) asm volatile("cp.async.wait_group 1;");
        else             asm volatile("cp.async.wait_group 0;");
        __syncthreads();

        const float4* pA = reinterpret_cast<const float4*>(gs->sA[s]);
        const float*  pB = gs->sB[s];
#pragma unroll
        for (int ks = 0; ks < 4; ks++) {
            float4 A0 = pA[aIdx0 + ks * 4];
            float4 A1 = pA[aIdx0 + ks * 4 + 8 * 17];
            uint32_t ahi[4] = {__float_as_uint(A0.x), __float_as_uint(A1.x),
                               __float_as_uint(A0.z), __float_as_uint(A1.z)};
            uint32_t alo[4] = {__float_as_uint(A0.y), __float_as_uint(A1.y),
                               __float_as_uint(A0.w), __float_as_uint(A1.w)};
            float4 Bv = *reinterpret_cast<const float4*>(&pB[(nwl * 4 + ks) * 128 + lane * 4]);
            uint32_t bh[2] = {__float_as_uint(Bv.x), __float_as_uint(Bv.y)};
            uint32_t bl[2] = {__float_as_uint(Bv.z), __float_as_uint(Bv.w)};
            mma_tf32(acc, ahi, bh);
            mma_tf32(acc, alo, bh);
            mma_tf32(acc, ahi, bl);
        }
        if (it + 2 < nC) stage((it + 2) % 3, cBeg + it + 2);
    }
    __syncthreads();   // drain last compute before reusing smem

    // ---- epilogue: C fragments -> smem -> fused LSTM cell ----
    float* g32 = reinterpret_cast<float*>(dynbuf);   // [32][32]
    {
        const int r0 = mw * 16 + (lane >> 2);
        const int col = nwl * 8 + (lane & 3) * 2;
        g32[r0 * 32 + col]           = acc[0];
        g32[r0 * 32 + col + 1]       = acc[1];
        g32[(r0 + 8) * 32 + col]     = acc[2];
        g32[(r0 + 8) * 32 + col + 1] = acc[3];
    }
    __syncthreads();
    {
        int b = tid >> 3;            // 0..31 local batch
        int u = tid & 7;             // local unit
        float4 gg = *reinterpret_cast<const float4*>(&g32[b * 32 + u * 4]);
        float4 bb = *reinterpret_cast<const float4*>(&g_bias[bn0 + u * 4]);
        float gi = gg.x + bb.x;
        float gf = gg.y + bb.y;
        float gc = gg.z + bb.z;
        float go = gg.w + bb.w;
        float si = 1.f / (1.f + expf(-gi));
        float sf = 1.f / (1.f + expf(-gf));
        float so = 1.f / (1.f + expf(-go));
        float tg = tanhf(gc);
        int bg = bm0 + b;
        int j = bn * 8 + u;
        float cold = g_c[bg * HID + j];
        float cnew = sf * cold + si * tg;
        g_c[bg * HID + j] = cnew;
        float hv = so * tanhf(cnew);
        hnew[bg * HID + j] = hv;
        int jp = bn * 8 + (((u & 3) << 1) | ((u >> 2) & 1));  // permk within 8
        hnewHL[bg * HID + jp] = splitHL(hv);
    }
    __threadfence();
    __syncthreads();
    if (tid == 0) atomicAdd(&g_cnt[t * 4 + bm], 1);   // release h for this bm-group

    if (bx >= 64) return;

    // ================= K2 phase: readout + stack + log-softmax ==============
    K2S* k2 = reinterpret_cast<K2S*>(dynbuf);
    const int b0 = bx * 2;
    const int grp = bx >> 4;
    if (tid == 0) {
        while (atomicAdd(&g_cnt[t * 4 + grp], 0) < 64) {}
    }
    __syncthreads();
    __threadfence();

    const float* __restrict__ h = g_h[cur ^ 1];

#pragma unroll
    for (int i = 0; i < 4; i++) {
        int idx = tid + i * 256;
        k2->hsh[idx >> 9][idx & 511] = h[(b0 + (idx >> 9)) * HID + (idx & 511)];
    }
    __syncthreads();

    // readout with 4 independent k-chunk accumulator chains per batch
    if (tid < RDIM) {
        const int r = tid;
        float c00 = br[r], c01 = 0.f, c02 = 0.f, c03 = 0.f;
        float c10 = c00,   c11 = 0.f, c12 = 0.f, c13 = 0.f;
#pragma unroll 4
        for (int k = 0; k < 128; k++) {
            float w0 = g_WrT[(k      ) * RDIM + r];
            float w1 = g_WrT[(k + 128) * RDIM + r];
            float w2 = g_WrT[(k + 256) * RDIM + r];
            float w3 = g_WrT[(k + 384) * RDIM + r];
            c00 = fmaf(k2->hsh[0][k      ], w0, c00);
            c01 = fmaf(k2->hsh[0][k + 128], w1, c01);
            c02 = fmaf(k2->hsh[0][k + 256], w2, c02);
            c03 = fmaf(k2->hsh[0][k + 384], w3, c03);
            c10 = fmaf(k2->hsh[1][k      ], w0, c10);
            c11 = fmaf(k2->hsh[1][k + 128], w1, c11);
            c12 = fmaf(k2->hsh[1][k + 256], w2, c12);
            c13 = fmaf(k2->hsh[1][k + 384], w3, c13);
        }
        float a0 = (c00 + c01) + (c02 + c03);
        float a1 = (c10 + c11) + (c12 + c13);
        k2->osh[0][r] = a0; k2->osh[1][r] = a1;
        if (r < STK) {
            g_V[((size_t)(b0 + 0) * MAXT + t) * STK + r] = a0;
            g_V[((size_t)(b0 + 1) * MAXT + t) * STK + r] = a1;
        }
    }
    __syncthreads();
    if (tid < 2) {
        k2->s_ut[tid] = 1.f / (1.f + expf(-k2->osh[tid][RDIM - 2]));
        k2->s_dt[tid] = 1.f / (1.f + expf(-k2->osh[tid][RDIM - 1]));
    }
    __syncthreads();

    const int n = t + 1;
    const int nc = (n + 31) >> 5;

    for (int bi = 0; bi < 2; bi++) {
        const int b = b0 + bi;
        for (int c = warp; c * 32 < n; c += 8) {
            int tau = c * 32 + lane;
            float v = (tau < n) ? g_s[b * MAXT + tau] : 0.f;
            if (tau < n) k2->sorig[tau] = v;
#pragma unroll
            for (int d = 1; d < 32; d <<= 1) {
                float o = __shfl_down_sync(0xffffffffu, v, d);
                if (lane + d < 32) v += o;
            }
            if (tau < n) k2->ssuf[tau] = v;
            if (lane == 0) k2->ctot[c] = v;
        }
        __syncthreads();
        if (tid == 0) {
            float run = 0.f;
            for (int c = nc - 1; c >= 0; c--) {
                float tc = k2->ctot[c];
                k2->ctot[c] = run;
                run += tc;
            }
        }
        __syncthreads();
        {
            float ut = k2->s_ut[bi], dt = k2->s_dt[bi];
            for (int tau = tid; tau < n; tau += 256) {
                float so_ = k2->sorig[tau];
                float prod = (k2->ssuf[tau] + k2->ctot[tau >> 5]) - so_;
                float sp = fmaxf(0.f, so_ - fmaxf(0.f, ut - prod));
                if (tau == t) sp = dt;
                float inner = fmaxf(0.f, 1.f - prod - sp);
                k2->aA[tau] = fminf(sp, inner);
                g_s[b * MAXT + tau] = sp;
            }
        }
        __syncthreads();
        {
            int d = tid & 63;
            int grp4 = tid >> 6;
            float racc = 0.f;
            for (int tau = grp4; tau < n; tau += 4)
                racc = fmaf(k2->aA[tau], g_V[((size_t)b * MAXT + tau) * STK + d], racc);
            k2->part[grp4][d] = racc;
        }
        __syncthreads();
        if (tid < STK) {
            float rv = k2->part[0][tid] + k2->part[1][tid] + k2->part[2][tid] + k2->part[3][tid];
            g_rtHL[b * STK + permk(tid)] = splitHL(rv);
        }
        __syncthreads();
    }

    if (t >= OUT_T0) {
        const int bi = tid >> 7;
        const int q = tid & 127;
        float v = k2->osh[bi][STK + q];
        float m = v;
#pragma unroll
        for (int d = 16; d; d >>= 1) m = fmaxf(m, __shfl_xor_sync(0xffffffffu, m, d));
        if (lane == 0) k2->redm[warp] = m;
        __syncthreads();
        if (tid < 2)
            k2->redv[tid] = fmaxf(fmaxf(k2->redm[tid * 4 + 0], k2->redm[tid * 4 + 1]),
                                  fmaxf(k2->redm[tid * 4 + 2], k2->redm[tid * 4 + 3]));
        __syncthreads();
        float mm = k2->redv[bi];
        float e = expf(v - mm);
        float s = e;
#pragma unroll
        for (int d = 16; d; d >>= 1) s += __shfl_xor_sync(0xffffffffu, s, d);
        if (lane == 0) k2->redm[warp] = s;
        __syncthreads();
        if (tid < 2)
            k2->redl[tid] = k2->redv[tid] + logf(k2->redm[tid * 4 + 0] + k2->redm[tid * 4 + 1] +
                                                 k2->redm[tid * 4 + 2] + k2->redm[tid * 4 + 3]);
        __syncthreads();
        int b = b0 + bi;
        out[((size_t)(t - OUT_T0) * BATCH + b) * IN_DIM + q] = v - k2->redl[bi];
    }
}

// ---------------- launch ----------------
extern "C" void kernel_launch(void* const* d_in, const int* in_sizes, int n_in,
                              void* d_out, int out_size)
{
    (void)in_sizes; (void)n_in; (void)out_size;
    const float* x   = (const float*)d_in[0];
    const float* Wih = (const float*)d_in[1];
    const float* bih = (const float*)d_in[2];
    const float* Whh = (const float*)d_in[3];
    const float* bhh = (const float*)d_in[4];
    const float* Wr  = (const float*)d_in[5];
    const float* br  = (const float*)d_in[6];
    float* out = (float*)d_out;

    // raise dynamic smem limit (idempotent; host-side, not a stream op)
    cudaFuncSetAttribute(k_step, cudaFuncAttributeMaxDynamicSharedMemorySize,
                         (int)sizeof(GS));

    k_prep<<<512, 256>>>(x, Wih, bih, Whh, bhh, Wr);

    for (int t = 0; t < NSTEPS; t++) {
        k_step<<<256, 256, sizeof(GS)>>>(t, br, out);
    }
}